// round 3
// baseline (speedup 1.0000x reference)
#include <cuda_runtime.h>
#include <cstdint>

#define NN 64
#define TT 5
#define VV 64
#define FF 256
#define TMID 2   // T//2

typedef unsigned long long u64;

__device__ __forceinline__ u64 add_f32x2(u64 a, u64 b) {
    u64 d; asm("add.rn.f32x2 %0, %1, %2;" : "=l"(d) : "l"(a), "l"(b)); return d;
}
__device__ __forceinline__ u64 fma_f32x2(u64 a, u64 b, u64 c) {
    u64 d; asm("fma.rn.f32x2 %0, %1, %2, %3;" : "=l"(d) : "l"(a), "l"(b), "l"(c)); return d;
}
__device__ __forceinline__ u64 pack2(float v) {
    u64 d; asm("mov.b64 %0, {%1, %1};" : "=l"(d) : "f"(v)); return d;
}

#define ABS2_MASK 0x7FFFFFFF7FFFFFFFULL

// Grid = 128 blocks (64 graphs x 2 halves), 512 threads each.
// Block owns 32 complete rows i of graph n's 64x64 similarity matrix.
// Thread layout: warp w covers rows {2w, 2w+1} of the half; lane>>4 selects
// the row, (lane&15)*4 selects a float4 of j. Row sums (== reference column
// sums by exact symmetry of S) reduce within 16-lane groups.
__global__ __launch_bounds__(512, 1)
void gl_kernel(const float* __restrict__ x,
               const float* __restrict__ a,
               float* __restrict__ out) {
    extern __shared__ float sm[];
    float* xsT = sm;                        // [FF][VV] transposed slice, 64 KB
    u64*   a2s = (u64*)(sm + FF * VV);      // [FF] packed (a_f, a_f), 2 KB

    const int b    = blockIdx.x;
    const int n    = b >> 1;
    const int half = b & 1;
    const int tid  = threadIdx.x;

    const float* xm = x + ((size_t)n * TT + TMID) * (size_t)(VV * FF);

    // ---- Stage xm[n] transposed: xsT[f*VV + v] = xm[v*FF + f] ----
    const float4* x4 = (const float4*)xm;
    #pragma unroll
    for (int idx = tid; idx < VV * (FF / 4); idx += 512) {
        int v  = idx >> 6;          // FF/4 == 64
        int f4 = idx & 63;
        float4 val = x4[v * (FF / 4) + f4];
        int f = f4 * 4;
        xsT[(f + 0) * VV + v] = val.x;
        xsT[(f + 1) * VV + v] = val.y;
        xsT[(f + 2) * VV + v] = val.z;
        xsT[(f + 3) * VV + v] = val.w;
    }
    if (tid < FF) a2s[tid] = pack2(a[tid]);
    __syncthreads();

    const int warp  = tid >> 5;
    const int lane  = tid & 31;
    const int i_idx = half * 32 + (warp << 1) + (lane >> 4); // row within graph
    const int j0    = (lane & 15) << 2;                      // 4 j's per lane

    u64 acc01 = 0, acc23 = 0;  // f32x2 accumulators = {0.0f, 0.0f}

    // ---- Main accumulation over f (packed f32x2) ----
    #pragma unroll 4
    for (int f = 0; f < FF; f++) {
        const float* row = &xsT[f * VV];
        ulonglong2 xj = *(const ulonglong2*)&row[j0];  // LDS.128, conflict-free
        float xin = -row[i_idx];                       // broadcast (2 addrs/warp)
        u64 av2   = a2s[f];                            // LDS.64 broadcast
        u64 xin2  = pack2(xin);

        u64 d01 = add_f32x2(xj.x, xin2) & ABS2_MASK;   // |xj - xi| (== |xi - xj|)
        u64 d23 = add_f32x2(xj.y, xin2) & ABS2_MASK;
        acc01 = fma_f32x2(av2, d01, acc01);
        acc23 = fma_f32x2(av2, d23, acc23);
    }

    // ---- exp, 16-lane row reduce, normalize, store float4 ----
    const float LOG2E = 1.4426950408889634f;
    float s0 = exp2f(__uint_as_float((unsigned)(acc01      )) * LOG2E);
    float s1 = exp2f(__uint_as_float((unsigned)(acc01 >> 32)) * LOG2E);
    float s2 = exp2f(__uint_as_float((unsigned)(acc23      )) * LOG2E);
    float s3 = exp2f(__uint_as_float((unsigned)(acc23 >> 32)) * LOG2E);

    float r = (s0 + s1) + (s2 + s3);
    #pragma unroll
    for (int off = 8; off > 0; off >>= 1)
        r += __shfl_xor_sync(0xFFFFFFFFu, r, off);   // stays within 16-lane group
    float inv = 1.0f / r;

    float4 o;
    o.x = s0 * inv; o.y = s1 * inv; o.z = s2 * inv; o.w = s3 * inv;
    *(float4*)&out[((size_t)(n * VV + i_idx)) * VV + j0] = o;
}

extern "C" void kernel_launch(void* const* d_in, const int* in_sizes, int n_in,
                              void* d_out, int out_size) {
    const float* x = (const float*)d_in[0];   // (64,5,64,256) float32
    const float* a = (const float*)d_in[1];   // (256,1) float32
    float* out = (float*)d_out;               // (64,64,64) float32

    const int smem_bytes = FF * VV * (int)sizeof(float) + FF * (int)sizeof(u64);
    cudaFuncSetAttribute(gl_kernel, cudaFuncAttributeMaxDynamicSharedMemorySize,
                         smem_bytes);
    gl_kernel<<<NN * 2, 512, smem_bytes>>>(x, a, out);
}